// round 3
// baseline (speedup 1.0000x reference)
#include <cuda_runtime.h>
#include <cuda_bf16.h>

// HDC token encoder:
//   out[b,i,d] = item_memory[token_ids[b,i], (d - i) mod D] / ||row||_2
// Entries are exactly +/-1 -> ||row|| == sqrt(10000) == 100 exactly.
// => out = cyclically-rolled gathered row * 0.01f. Pure memory movement.
//
// R2 lesson: misaligned scalar loads cost 2 L1 wavefronts / 128B (L1 at 80.5%).
// This version: decompose shift i = 4s + r. Both LDG and STG are aligned
// float4 (1 wf / 128B); the sub-chunk rotation r is done with warp shuffles
// (lane t-1's chunk is thread t's "previous" chunk) + 1 predicated lane-0
// load, specialized at compile time for r in {0,1,2,3} (uniform per CTA).

#define B_ 8
#define S_ 2048
#define V_ 256
#define D_ 10000
#define CHUNKS_ (D_ / 4)        // 2500 float4 chunks per row
#define NITER_ 10               // ceil(2500 / 256)

template<int R>
__device__ __forceinline__ void encode_row(const float4* __restrict__ src4,
                                           float4* __restrict__ dst4,
                                           int s)
{
    const int lane = threadIdx.x & 31;

    #pragma unroll
    for (int it = 0; it < NITER_; ++it) {
        const int g = (it << 8) + threadIdx.x;     // output chunk index
        const bool active = (g < CHUNKS_);

        int jB = g - s;                            // s < 512, g < 2560
        if (jB < 0) jB += CHUNKS_;

        float4 Bv = make_float4(0.f, 0.f, 0.f, 0.f);
        if (active) Bv = __ldg(&src4[jB]);

        float4 v;
        if (R == 0) {
            v = Bv;                                // pure chunk rotation
        } else {
            // A = previous source chunk = lane-1's Bv (only R components needed)
            float Aw = __shfl_up_sync(0xffffffffu, Bv.w, 1);
            float Az = (R >= 2) ? __shfl_up_sync(0xffffffffu, Bv.z, 1) : 0.f;
            float Ay = (R >= 3) ? __shfl_up_sync(0xffffffffu, Bv.y, 1) : 0.f;
            if (lane == 0) {                       // warp-boundary chunk
                int jA = g - s - 1;
                if (jA < 0) jA += CHUNKS_;
                const float4 Af = __ldg(&src4[jA]);
                Aw = Af.w; Az = Af.z; Ay = Af.y;
            }
            if (R == 1) v = make_float4(Aw, Bv.x, Bv.y, Bv.z);
            if (R == 2) v = make_float4(Az, Aw, Bv.x, Bv.y);
            if (R == 3) v = make_float4(Ay, Az, Aw, Bv.x);
        }

        if (active) {
            v.x *= 0.01f; v.y *= 0.01f; v.z *= 0.01f; v.w *= 0.01f;
            __stcs(&dst4[g], v);                   // streaming: output never re-read
        }
    }
}

__global__ __launch_bounds__(256, 8)
void hdc_encode_kernel(const int* __restrict__ token_ids,
                       const float* __restrict__ item_memory,
                       float* __restrict__ out)
{
    const int row = blockIdx.x;                    // row = b*S + i
    const int i   = row & (S_ - 1);
    const int tok = __ldg(&token_ids[row]);

    const float4* __restrict__ src4 =
        reinterpret_cast<const float4*>(item_memory + (long long)tok * D_);
    float4* __restrict__ dst4 =
        reinterpret_cast<float4*>(out + (long long)row * D_);

    const int s = i >> 2;
    switch (i & 3) {
        case 0: encode_row<0>(src4, dst4, s); break;
        case 1: encode_row<1>(src4, dst4, s); break;
        case 2: encode_row<2>(src4, dst4, s); break;
        default: encode_row<3>(src4, dst4, s); break;
    }
}

extern "C" void kernel_launch(void* const* d_in, const int* in_sizes, int n_in,
                              void* d_out, int out_size)
{
    const int*   token_ids   = (const int*)  d_in[0];   // (B, S) int32
    const float* item_memory = (const float*)d_in[1];   // (V, D) float32
    float*       out         = (float*)d_out;           // (B, S, D) float32

    (void)in_sizes; (void)n_in; (void)out_size;

    hdc_encode_kernel<<<B_ * S_, 256>>>(token_ids, item_memory, out);
}

// round 4
// speedup vs baseline: 1.0091x; 1.0091x over previous
#include <cuda_runtime.h>
#include <cuda_bf16.h>

// HDC token encoder:
//   out[b,i,d] = item_memory[token_ids[b,i], (d - i) mod D] / ||row||_2
// Entries are exactly +/-1 -> ||row|| == sqrt(10000) == 100 exactly
// => out = cyclically-rolled gathered row * 0.01f. Pure memory movement.
//
// R3 lesson: vectorized/shuffled loads don't reduce L1 wavefront cost.
// R4 design: exploit token reuse (avg 64 rows/token). CTA (tok, slot) stages
// the token row in SMEM once, then emits its ~8 claimed rows:
//   - row claim:  idx ≡ slot (mod 8) AND token_ids[idx] == tok  (deterministic
//                 partition, no prepass kernels, no atomics ordering issues)
//   - rotation happens on the SMEM read side: lane-consecutive LDS.32 is
//     conflict-free regardless of the shift
//   - stores are aligned coalesced streaming STG.32
// L2 read traffic drops 640MB -> ~85MB; DRAM writes (640MB) become the wall.

#define B_ 8
#define S_ 2048
#define V_ 256
#define D_ 10000
#define NROWS_   (B_ * S_)          // 16384
#define SLOTS_   8
#define PER_SLOT (NROWS_ / SLOTS_)  // 2048 (worst-case rows per CTA)
#define CHUNKS_  (D_ / 4)           // 2500 float4 chunks

__global__ __launch_bounds__(256, 4)
void hdc_encode_grouped(const int* __restrict__ token_ids,
                        const float* __restrict__ item_memory,
                        float* __restrict__ out)
{
    __shared__ __align__(16) float s_row[D_];   // 40000 B
    __shared__ int s_list[PER_SLOT];            //  8192 B (worst-case safe)
    __shared__ int s_cnt;

    const int tok  = blockIdx.x >> 3;
    const int slot = blockIdx.x & (SLOTS_ - 1);
    const int tid  = threadIdx.x;

    if (tid == 0) s_cnt = 0;
    __syncthreads();

    // Claim rows: idx = k*8 + slot, token_ids[idx] == tok.
    // Every row idx belongs to exactly one (tok, slot) CTA.
    #pragma unroll
    for (int it = 0; it < PER_SLOT / 256; ++it) {       // 8 iterations
        const int k   = (it << 8) + tid;
        const int idx = (k << 3) + slot;
        if (__ldg(&token_ids[idx]) == tok) {
            const int p = atomicAdd(&s_cnt, 1);         // order irrelevant
            s_list[p] = idx;
        }
    }
    __syncthreads();
    const int cnt = s_cnt;
    if (cnt == 0) return;                               // nothing to emit

    // Stage the token row in SMEM once, pre-scaled by 1/||row|| = 0.01.
    const float4* __restrict__ src4 =
        reinterpret_cast<const float4*>(item_memory + (long long)tok * D_);
    float4* s_row4 = reinterpret_cast<float4*>(s_row);
    for (int g = tid; g < CHUNKS_; g += 256) {
        float4 v = __ldg(&src4[g]);
        v.x *= 0.01f; v.y *= 0.01f; v.z *= 0.01f; v.w *= 0.01f;
        s_row4[g] = v;
    }
    __syncthreads();

    // Emit each claimed output row: rotated SMEM read, aligned streaming store.
    for (int m = 0; m < cnt; ++m) {
        const int r = s_list[m];                        // LDS broadcast
        const int i = r & (S_ - 1);                     // position = row mod S
        float* __restrict__ dst = out + (long long)r * D_;

        int d = tid;
        #pragma unroll 13
        for (int k = 0; k < 39; ++k, d += 256) {        // 39*256 = 9984
            int j = d - i; if (j < 0) j += D_;
            __stcs(&dst[d], s_row[j]);
        }
        if (d < D_) {                                   // tail: threads 0..15
            int j = d - i; if (j < 0) j += D_;
            __stcs(&dst[d], s_row[j]);
        }
    }
}

extern "C" void kernel_launch(void* const* d_in, const int* in_sizes, int n_in,
                              void* d_out, int out_size)
{
    const int*   token_ids   = (const int*)  d_in[0];   // (B, S) int32
    const float* item_memory = (const float*)d_in[1];   // (V, D) float32
    float*       out         = (float*)d_out;           // (B, S, D) float32

    (void)in_sizes; (void)n_in; (void)out_size;

    hdc_encode_grouped<<<V_ * SLOTS_, 256>>>(token_ids, item_memory, out);
}